// round 16
// baseline (speedup 1.0000x reference)
#include <cuda_runtime.h>
#include <cuda_bf16.h>
#include <cuda_fp16.h>

#define Bd   4096
#define Sd   512
#define Ad   64
#define H1d  1024
#define H2d  512
#define EPSf 1e-8f
#define TK   16
#define NROWS (Bd * Ad)

typedef unsigned long long ull;
typedef unsigned int u32;

// ------------------------- device scratch (no allocs allowed) --------------
__device__ float g_G[Bd * H1d];              // 64*(G*invn + b1)  (pre-scaled)
__device__ __half g_AWTt2[Ad * H1d];         // [a][o] fp16
__device__ float g_invn[Bd];
__device__ __half g_W2h[H2d * H1d];          // fp16(W2)
__device__ __half g_h1[(size_t)NROWS * H1d]; // 512 MB: scaled fp16 h1 rows
__device__ float g_rinv[NROWS];              // 1/(||h64|| + 64*eps)

// ------------------------- helpers -----------------------------------------
__device__ __forceinline__ u32 smem_u32(const void* p) {
    u32 a;
    asm("{ .reg .u64 t; cvta.to.shared.u64 t, %1; cvt.u32.u64 %0, t; }"
        : "=r"(a) : "l"(p));
    return a;
}
__device__ __forceinline__ ull pk2(float lo, float hi) {
    ull r;
    asm("mov.b64 %0, {%1, %2};" : "=l"(r)
        : "r"(__float_as_uint(lo)), "r"(__float_as_uint(hi)));
    return r;
}
__device__ __forceinline__ void upk2(ull v, float& lo, float& hi) {
    unsigned a, b;
    asm("mov.b64 {%0, %1}, %2;" : "=r"(a), "=r"(b) : "l"(v));
    lo = __uint_as_float(a); hi = __uint_as_float(b);
}
__device__ __forceinline__ ull ffma2(ull a, ull b, ull c) {
    ull d;
    asm("fma.rn.f32x2 %0, %1, %2, %3;" : "=l"(d) : "l"(a), "l"(b), "l"(c));
    return d;
}
__device__ __forceinline__ u32 pkhf(float lo, float hi) {
    u32 r;
    asm("cvt.rn.f16x2.f32 %0, %1, %2;" : "=r"(r) : "f"(hi), "f"(lo));
    return r;
}
__device__ __forceinline__ void cpasync16(u32 dst, const void* src) {
    asm volatile("cp.async.cg.shared.global [%0], [%1], 16;"
                 :: "r"(dst), "l"(src) : "memory");
}
__device__ __forceinline__ void ldm4(u32* r, u32 addr) {
    asm volatile("ldmatrix.sync.aligned.m8n8.x4.shared.b16 {%0,%1,%2,%3}, [%4];"
                 : "=r"(r[0]), "=r"(r[1]), "=r"(r[2]), "=r"(r[3]) : "r"(addr));
}
__device__ __forceinline__ void mma16816(float* c, const u32* a, u32 b0, u32 b1) {
    asm volatile(
        "mma.sync.aligned.m16n8k16.row.col.f32.f16.f16.f32 "
        "{%0,%1,%2,%3}, {%4,%5,%6,%7}, {%8,%9}, {%0,%1,%2,%3};"
        : "+f"(c[0]), "+f"(c[1]), "+f"(c[2]), "+f"(c[3])
        : "r"(a[0]), "r"(a[1]), "r"(a[2]), "r"(a[3]), "r"(b0), "r"(b1));
}
// 128B-row SW128 tile addressing: row has 8 16B k-groups
__device__ __forceinline__ u32 toff(int row, int g) {
    return (u32)(row * 128 + ((g ^ (row & 7)) << 4));
}

// ---------------------------------------------------------------------------
// Prep: AWT a-major fp16 gather + W2 fp16 convert
// ---------------------------------------------------------------------------
__global__ void k_prep(const float* __restrict__ W1,
                       const float* __restrict__ W2) {
    int i = blockIdx.x * 256 + threadIdx.x;
    if (i < Ad * H1d) {
        int a = i >> 10, o = i & 1023;
        g_AWTt2[i] = __float2half_rn(W1[o * 576 + 512 + a]);
    }
    int j = i - Ad * H1d;
    if (j >= 0 && j < H2d * H1d) {
        g_W2h[j] = __float2half_rn(W2[j]);
    }
}
__global__ void k_invn(const float* __restrict__ states) {
    int w    = (blockIdx.x * blockDim.x + threadIdx.x) >> 5;
    int lane = threadIdx.x & 31;
    if (w >= Bd) return;
    const float* s = states + w * Sd;
    float acc = 0.f;
#pragma unroll 4
    for (int j = lane; j < Sd; j += 32) { float v = s[j]; acc += v * v; }
#pragma unroll
    for (int off = 16; off; off >>= 1) acc += __shfl_xor_sync(0xffffffffu, acc, off);
    if (lane == 0) g_invn[w] = 1.f / (sqrtf(acc + 1.f) + EPSf);
}

// ---------------------------------------------------------------------------
// g_G[b][o] = 64 * ((states[b,:].W1[o,:512]) * invn[b] + b1[o])
// ---------------------------------------------------------------------------
__global__ void __launch_bounds__(256) k_gemmG(const float* __restrict__ states,
                                               const float* __restrict__ W1,
                                               const float* __restrict__ b1) {
    __shared__ __align__(16) float As[2][TK][128];
    __shared__ __align__(16) float Bs[2][TK][128];

    int b0  = (blockIdx.x >> 3) * 128;
    int o0  = (blockIdx.x & 7) * 128;
    int tid = threadIdx.x;
    int tm  = tid >> 4, tn = tid & 15;

    ull acc[4][8];
#pragma unroll
    for (int i = 0; i < 4; i++)
#pragma unroll
        for (int j = 0; j < 8; j++) acc[i][j] = 0ull;

    auto loadTile = [&](int c, int buf) {
        int k0 = c * TK;
#pragma unroll
        for (int it = 0; it < 2; it++) {
            int e = tid + it * 256;
            int r = e >> 2, kq = (e & 3) * 4;
            float4 va = *(const float4*)&states[(b0 + r) * Sd + k0 + kq];
            As[buf][kq + 0][r] = va.x; As[buf][kq + 1][r] = va.y;
            As[buf][kq + 2][r] = va.z; As[buf][kq + 3][r] = va.w;
            float4 vb = *(const float4*)&W1[(o0 + r) * 576 + k0 + kq];
            Bs[buf][kq + 0][r] = vb.x; Bs[buf][kq + 1][r] = vb.y;
            Bs[buf][kq + 2][r] = vb.z; Bs[buf][kq + 3][r] = vb.w;
        }
    };

    loadTile(0, 0);
    __syncthreads();
    const int NC = Sd / TK;
    for (int c = 0; c < NC; c++) {
        int buf = c & 1;
        if (c + 1 < NC) loadTile(c + 1, buf ^ 1);
#pragma unroll
        for (int kk = 0; kk < TK; kk++) {
            ull a2[4];
            const ull* ap = (const ull*)&As[buf][kk][tm * 8];
#pragma unroll
            for (int i = 0; i < 4; i++) a2[i] = ap[i];
            float4 bv0 = *(const float4*)&Bs[buf][kk][tn * 8];
            float4 bv1 = *(const float4*)&Bs[buf][kk][tn * 8 + 4];
            ull b2r[8];
            b2r[0] = pk2(bv0.x, bv0.x); b2r[1] = pk2(bv0.y, bv0.y);
            b2r[2] = pk2(bv0.z, bv0.z); b2r[3] = pk2(bv0.w, bv0.w);
            b2r[4] = pk2(bv1.x, bv1.x); b2r[5] = pk2(bv1.y, bv1.y);
            b2r[6] = pk2(bv1.z, bv1.z); b2r[7] = pk2(bv1.w, bv1.w);
#pragma unroll
            for (int i = 0; i < 4; i++)
#pragma unroll
                for (int j = 0; j < 8; j++)
                    acc[i][j] = ffma2(a2[i], b2r[j], acc[i][j]);
        }
        __syncthreads();
    }

    float4 b1a = *(const float4*)&b1[o0 + tn * 8];
    float4 b1b = *(const float4*)&b1[o0 + tn * 8 + 4];
    float bb[8] = {b1a.x, b1a.y, b1a.z, b1a.w, b1b.x, b1b.y, b1b.z, b1b.w};
#pragma unroll
    for (int i = 0; i < 4; i++) {
        int m0 = b0 + tm * 8 + i * 2;
        float inv0 = g_invn[m0], inv1 = g_invn[m0 + 1];
        float lo[8], hi[8];
#pragma unroll
        for (int j = 0; j < 8; j++) {
            upk2(acc[i][j], lo[j], hi[j]);
            lo[j] = fmaf(lo[j], inv0, bb[j]) * 64.0f;
            hi[j] = fmaf(hi[j], inv1, bb[j]) * 64.0f;
        }
        float* p0 = &g_G[(m0 + 0) * H1d + o0 + tn * 8];
        float* p1 = &g_G[(m0 + 1) * H1d + o0 + tn * 8];
        *(float4*)p0       = make_float4(lo[0], lo[1], lo[2], lo[3]);
        *(float4*)(p0 + 4) = make_float4(lo[4], lo[5], lo[6], lo[7]);
        *(float4*)p1       = make_float4(hi[0], hi[1], hi[2], hi[3]);
        *(float4*)(p1 + 4) = make_float4(hi[4], hi[5], hi[6], hi[7]);
    }
}

// ---------------------------------------------------------------------------
// k_genA: one warp per (b, a) row. h64[o] = relu(g64[b][o] + 64*inv*awt[a][o])
// -> fp16 row of g_h1, plus g_rinv = 1/(||h64|| + 64*eps).
// ---------------------------------------------------------------------------
__global__ void __launch_bounds__(256) k_genA() {
    int w    = (blockIdx.x * blockDim.x + threadIdx.x) >> 5;
    int lane = threadIdx.x & 31;
    if (w >= NROWS) return;
    int b = w >> 6, a = w & 63;
    float inv64 = g_invn[b] * 64.0f;
    const float*  g  = g_G + (size_t)b * H1d;
    const __half* aw = g_AWTt2 + (size_t)a * H1d;
    __half* dst = g_h1 + (size_t)w * H1d;

    float ss = 0.f;
#pragma unroll
    for (int it = 0; it < 4; it++) {
        int o = it * 256 + lane * 8;
        float4 g0 = *(const float4*)(g + o);
        float4 g1 = *(const float4*)(g + o + 4);
        uint4 wq = *(const uint4*)(aw + o);
        float2 w01 = __half22float2(*(const __half2*)&wq.x);
        float2 w23 = __half22float2(*(const __half2*)&wq.y);
        float2 w45 = __half22float2(*(const __half2*)&wq.z);
        float2 w67 = __half22float2(*(const __half2*)&wq.w);
        float h[8];
        h[0] = fmaxf(fmaf(inv64, w01.x, g0.x), 0.f);
        h[1] = fmaxf(fmaf(inv64, w01.y, g0.y), 0.f);
        h[2] = fmaxf(fmaf(inv64, w23.x, g0.z), 0.f);
        h[3] = fmaxf(fmaf(inv64, w23.y, g0.w), 0.f);
        h[4] = fmaxf(fmaf(inv64, w45.x, g1.x), 0.f);
        h[5] = fmaxf(fmaf(inv64, w45.y, g1.y), 0.f);
        h[6] = fmaxf(fmaf(inv64, w67.x, g1.z), 0.f);
        h[7] = fmaxf(fmaf(inv64, w67.y, g1.w), 0.f);
#pragma unroll
        for (int j = 0; j < 8; j++) ss = fmaf(h[j], h[j], ss);
        uint4 q;
        q.x = pkhf(h[0], h[1]); q.y = pkhf(h[2], h[3]);
        q.z = pkhf(h[4], h[5]); q.w = pkhf(h[6], h[7]);
        *(uint4*)(dst + o) = q;
    }
#pragma unroll
    for (int off = 16; off; off >>= 1) ss += __shfl_xor_sync(0xffffffffu, ss, off);
    if (lane == 0) g_rinv[w] = 1.f / (sqrtf(ss) + 64.0f * EPSf);
}

// ---------------------------------------------------------------------------
// Main kernel: pure GEMM, single pass. M=64 rows/CTA, N=512, K=1024 in 16
// chunks of 64. 512 threads (2m x 8n warp grid, 32x64 per warp). 1 CTA/SM.
// ---------------------------------------------------------------------------
#define SOFF_B2    0        // 512 f32
#define SOFF_WQ    2048     // 512 f32
#define SOFF_RINV  4096     // 64 f32
#define SOFF_SS    4352     // 512 f32 (q cross-warp partials)
#define SOFF_STG   7168
#define AF_OFF     0        // 64 rows x 128B = 8 KB
#define BF_OFF     8192     // 512 rows x 128B = 64 KB
#define STG_BYTES  73728    // 72 KB per stage
#define SMEM_TOTAL (SOFF_STG + 2 * STG_BYTES)   // 154624 B -> 1 CTA/SM

#define KC  64
#define NCH (H1d / KC)      // 16 chunks

__global__ void __launch_bounds__(512, 1)
k_main(const float* __restrict__ b2, const float* __restrict__ Wq,
       const float* __restrict__ bq, float* __restrict__ out) {
    extern __shared__ __align__(1024) char smem[];
    u32 sb = smem_u32(smem);
    int tid = threadIdx.x;
    int wid = tid >> 5, lane = tid & 31;
    int warp_m = wid >> 3, warp_n = wid & 7;       // 2 x 8 warp grid
    int bidx = blockIdx.x;
    int r0 = bidx * 64;

    float* b2s   = (float*)(smem + SOFF_B2);
    float* wqs   = (float*)(smem + SOFF_WQ);
    float* rinvs = (float*)(smem + SOFF_RINV);
    float* sss   = (float*)(smem + SOFF_SS);

    for (int i = tid; i < H2d; i += 512) { b2s[i] = b2[i]; wqs[i] = Wq[i]; }
    if (tid < 64) rinvs[tid] = g_rinv[r0 + tid];
    __syncthreads();

    // A loader: 64 rows x 64 k fp16 per chunk (8 KB = 512 granules)
    auto loadA = [&](int c, int buf) {
        u32 af = sb + SOFF_STG + buf * STG_BYTES + AF_OFF;
        const __half* h1 = g_h1 + (size_t)r0 * H1d + c * KC;
        int row = tid >> 3, g = tid & 7;
        cpasync16(af + toff(row, g), h1 + (size_t)row * H1d + g * 8);
    };
    // B loader: W2 fp16, 512 n-rows x 64 k per chunk (64 KB = 4096 granules)
    auto loadB = [&](int c, int buf) {
        u32 bf = sb + SOFF_STG + buf * STG_BYTES + BF_OFF;
        const __half* w2 = g_W2h + c * KC;
#pragma unroll
        for (int i = 0; i < 8; i++) {
            int e = tid + i * 512;
            int n = e >> 3, g = e & 7;
            cpasync16(bf + toff(n, g), w2 + (size_t)n * H1d + g * 8);
        }
    };

    int lt = lane & 15, lh = lane >> 4;
    float qacc[4] = {0.f, 0.f, 0.f, 0.f};

    float acc[2][8][4];
#pragma unroll
    for (int i = 0; i < 2; i++)
#pragma unroll
        for (int j = 0; j < 8; j++)
#pragma unroll
            for (int k = 0; k < 4; k++) acc[i][j][k] = 0.f;

    loadA(0, 0);
    loadB(0, 0);
    asm volatile("cp.async.commit_group;" ::: "memory");
    asm volatile("cp.async.wait_group 0;" ::: "memory");
    __syncthreads();

    for (int c = 0; c < NCH; c++) {
        int buf = c & 1;
        bool more = (c + 1 < NCH);
        if (more) {
            loadA(c + 1, buf ^ 1);
            loadB(c + 1, buf ^ 1);
            asm volatile("cp.async.commit_group;" ::: "memory");
        }

        u32 abase = sb + SOFF_STG + buf * STG_BYTES;
#pragma unroll
        for (int ks = 0; ks < 4; ks++) {
            int g = ks * 2 + lh;
            u32 ah[2][4];
#pragma unroll
            for (int mt = 0; mt < 2; mt++) {
                int row = warp_m * 32 + mt * 16 + lt;
                ldm4(ah[mt], abase + AF_OFF + toff(row, g));
            }
#pragma unroll
            for (int nb = 0; nb < 4; nb++) {
                int nrow = warp_n * 64 + nb * 16 + lt;
                u32 bh[4];
                ldm4(bh, abase + BF_OFF + toff(nrow, g));
#pragma unroll
                for (int mt = 0; mt < 2; mt++)
#pragma unroll
                    for (int s = 0; s < 2; s++)
                        mma16816(acc[mt][nb * 2 + s], ah[mt],
                                 bh[s], bh[s + 2]);
            }
        }
        asm volatile("cp.async.wait_group 0;" ::: "memory");
        __syncthreads();
    }

    // epilogue: q += relu(acc * rinv + b2) * Wq over this warp's 64 n
#pragma unroll
    for (int mt = 0; mt < 2; mt++) {
        int rlo = warp_m * 32 + mt * 16 + (lane >> 2);
        float rv0 = rinvs[rlo], rv1 = rinvs[rlo + 8];
#pragma unroll
        for (int nt = 0; nt < 8; nt++) {
            int n = warp_n * 64 + nt * 8 + (lane & 3) * 2;
            float bb0 = b2s[n], bb1 = b2s[n + 1];
            float w0 = wqs[n], w1 = wqs[n + 1];
            const float* cc = acc[mt][nt];
            qacc[mt * 2 + 0] += fmaxf(fmaf(cc[0], rv0, bb0), 0.f) * w0 +
                                fmaxf(fmaf(cc[1], rv0, bb1), 0.f) * w1;
            qacc[mt * 2 + 1] += fmaxf(fmaf(cc[2], rv1, bb0), 0.f) * w0 +
                                fmaxf(fmaf(cc[3], rv1, bb1), 0.f) * w1;
        }
    }

    // reduce q over the 4 lanes of each quad
#pragma unroll
    for (int off = 1; off <= 2; off <<= 1)
#pragma unroll
        for (int i = 0; i < 4; i++)
            qacc[i] += __shfl_xor_sync(0xffffffffu, qacc[i], off);

    if ((lane & 3) == 0) {
#pragma unroll
        for (int mt = 0; mt < 2; mt++)
#pragma unroll
            for (int hh = 0; hh < 2; hh++) {
                int row = warp_m * 32 + mt * 16 + hh * 8 + (lane >> 2);
                sss[row * 8 + warp_n] = qacc[mt * 2 + hh];
            }
    }
    __syncthreads();
    if (tid < 64) {
        float s = 0.f;
#pragma unroll
        for (int j = 0; j < 8; j++) s += sss[tid * 8 + j];
        out[r0 + tid] = s + __ldg(bq);
    }
}

// ---------------------------------------------------------------------------
extern "C" void kernel_launch(void* const* d_in, const int* in_sizes, int n_in,
                              void* d_out, int out_size) {
    const float* states = (const float*)d_in[0];
    const float* W1     = (const float*)d_in[1];
    const float* b1     = (const float*)d_in[2];
    const float* W2     = (const float*)d_in[3];
    const float* b2     = (const float*)d_in[4];
    const float* Wq     = (const float*)d_in[5];
    const float* bq     = (const float*)d_in[6];
    float* out = (float*)d_out;

    cudaFuncSetAttribute((const void*)k_main,
                         cudaFuncAttributeMaxDynamicSharedMemorySize, SMEM_TOTAL);

    k_invn<<<Bd / 8, 256>>>(states);
    k_prep<<<(Ad * H1d + H2d * H1d + 255) / 256, 256>>>(W1, W2);
    k_gemmG<<<(Bd / 128) * (H1d / 128), 256>>>(states, W1, b1);
    k_genA<<<NROWS / 8, 256>>>();
    k_main<<<Bd, 512, SMEM_TOTAL>>>(b2, Wq, bq, out);
}

// round 17
// speedup vs baseline: 1.1889x; 1.1889x over previous
#include <cuda_runtime.h>
#include <cuda_bf16.h>
#include <cuda_fp16.h>

#define Bd   4096
#define Sd   512
#define Ad   64
#define H1d  1024
#define H2d  512
#define EPSf 1e-8f
#define NROWS (Bd * Ad)

typedef unsigned long long ull;
typedef unsigned int u32;

// ------------------------- device scratch (no allocs allowed) --------------
__device__ float g_G[Bd * H1d];              // 64*(G*invn + b1)  (pre-scaled)
__device__ __half g_AWTt2[Ad * H1d];         // [a][o] fp16
__device__ float g_invn[Bd];
__device__ __half g_W2h[H2d * H1d];          // fp16(W2)
__device__ __half g_W1h[H1d * Sd];           // fp16(W1[:, :512])
__device__ __half g_Shi[Bd * Sd];            // fp16 hi(states)
__device__ __half g_Slo[Bd * Sd];            // fp16 lo(states)
__device__ __half g_h1[(size_t)NROWS * H1d]; // 512 MB: scaled fp16 h1 rows
__device__ float g_rinv[NROWS];              // 1/(||h64|| + 64*eps)

// ------------------------- helpers -----------------------------------------
__device__ __forceinline__ u32 smem_u32(const void* p) {
    u32 a;
    asm("{ .reg .u64 t; cvta.to.shared.u64 t, %1; cvt.u32.u64 %0, t; }"
        : "=r"(a) : "l"(p));
    return a;
}
__device__ __forceinline__ u32 pkhf(float lo, float hi) {
    u32 r;
    asm("cvt.rn.f16x2.f32 %0, %1, %2;" : "=r"(r) : "f"(hi), "f"(lo));
    return r;
}
__device__ __forceinline__ void cpasync16(u32 dst, const void* src) {
    asm volatile("cp.async.cg.shared.global [%0], [%1], 16;"
                 :: "r"(dst), "l"(src) : "memory");
}
__device__ __forceinline__ void ldm4(u32* r, u32 addr) {
    asm volatile("ldmatrix.sync.aligned.m8n8.x4.shared.b16 {%0,%1,%2,%3}, [%4];"
                 : "=r"(r[0]), "=r"(r[1]), "=r"(r[2]), "=r"(r[3]) : "r"(addr));
}
__device__ __forceinline__ void mma16816(float* c, const u32* a, u32 b0, u32 b1) {
    asm volatile(
        "mma.sync.aligned.m16n8k16.row.col.f32.f16.f16.f32 "
        "{%0,%1,%2,%3}, {%4,%5,%6,%7}, {%8,%9}, {%0,%1,%2,%3};"
        : "+f"(c[0]), "+f"(c[1]), "+f"(c[2]), "+f"(c[3])
        : "r"(a[0]), "r"(a[1]), "r"(a[2]), "r"(a[3]), "r"(b0), "r"(b1));
}
// 128B-row SW128 tile addressing: row has 8 16B k-groups
__device__ __forceinline__ u32 toff(int row, int g) {
    return (u32)(row * 128 + ((g ^ (row & 7)) << 4));
}

// ---------------------------------------------------------------------------
// Prep: AWT a-major fp16, W2 fp16, W1 fp16, states fp16 hi/lo split
// ---------------------------------------------------------------------------
__global__ void k_prep(const float* __restrict__ W1,
                       const float* __restrict__ W2,
                       const float* __restrict__ states) {
    int i = blockIdx.x * 256 + threadIdx.x;
    if (i < Ad * H1d) {
        int a = i >> 10, o = i & 1023;
        g_AWTt2[i] = __float2half_rn(W1[o * 576 + 512 + a]);
    }
    if (i < H2d * H1d) {
        g_W2h[i] = __float2half_rn(W2[i]);
    }
    if (i < H1d * Sd) {
        int o = i >> 9, s = i & 511;
        g_W1h[i] = __float2half_rn(W1[o * 576 + s]);
    }
    if (i < Bd * Sd) {
        float v = states[i];
        __half h = __float2half_rn(v);
        g_Shi[i] = h;
        g_Slo[i] = __float2half_rn(v - __half2float(h));
    }
}
__global__ void k_invn(const float* __restrict__ states) {
    int w    = (blockIdx.x * blockDim.x + threadIdx.x) >> 5;
    int lane = threadIdx.x & 31;
    if (w >= Bd) return;
    const float* s = states + w * Sd;
    float acc = 0.f;
#pragma unroll 4
    for (int j = lane; j < Sd; j += 32) { float v = s[j]; acc += v * v; }
#pragma unroll
    for (int off = 16; off; off >>= 1) acc += __shfl_xor_sync(0xffffffffu, acc, off);
    if (lane == 0) g_invn[w] = 1.f / (sqrtf(acc + 1.f) + EPSf);
}

// ---------------------------------------------------------------------------
// Tensor-core gemmG: g_G[b][o] = 64*((states.W1[o,:512]) * invn[b] + b1[o])
// A = states fp16 hi/lo (2 MMAs/k-step), B = fp16(W1). 64 b x 128 o per CTA.
// ---------------------------------------------------------------------------
#define GG_AHI   0
#define GG_ALO   8192
#define GG_B     16384
#define GG_STG   32768      // per-stage bytes
#define GG_SMEM  (2 * GG_STG)

__global__ void __launch_bounds__(256, 2) k_gemmG_tc(const float* __restrict__ b1) {
    extern __shared__ __align__(1024) char smem[];
    u32 sb = smem_u32(smem);
    int tid = threadIdx.x;
    int wid = tid >> 5, lane = tid & 31;
    int warp_m = wid >> 2, warp_n = wid & 3;       // 2 x 4
    int b0 = (blockIdx.x >> 3) * 64;
    int o0 = (blockIdx.x & 7) * 128;

    auto loadA = [&](int c, int buf) {
        u32 ah = sb + buf * GG_STG + GG_AHI;
        u32 al = sb + buf * GG_STG + GG_ALO;
        const __half* shi = g_Shi + (size_t)b0 * Sd + c * 64;
        const __half* slo = g_Slo + (size_t)b0 * Sd + c * 64;
#pragma unroll
        for (int i = 0; i < 2; i++) {
            int e = tid + i * 256;
            int row = e >> 3, g = e & 7;
            cpasync16(ah + toff(row, g), shi + (size_t)row * Sd + g * 8);
        }
#pragma unroll
        for (int i = 0; i < 2; i++) {
            int e = tid + i * 256;
            int row = e >> 3, g = e & 7;
            cpasync16(al + toff(row, g), slo + (size_t)row * Sd + g * 8);
        }
    };
    auto loadB = [&](int c, int buf) {
        u32 bf = sb + buf * GG_STG + GG_B;
        const __half* w1 = g_W1h + (size_t)o0 * Sd + c * 64;
#pragma unroll
        for (int i = 0; i < 4; i++) {
            int e = tid + i * 256;
            int n = e >> 3, g = e & 7;
            cpasync16(bf + toff(n, g), w1 + (size_t)n * Sd + g * 8);
        }
    };

    int lt = lane & 15, lh = lane >> 4;
    float acc[2][4][4];
#pragma unroll
    for (int i = 0; i < 2; i++)
#pragma unroll
        for (int j = 0; j < 4; j++)
#pragma unroll
            for (int k = 0; k < 4; k++) acc[i][j][k] = 0.f;

    loadA(0, 0);
    loadB(0, 0);
    asm volatile("cp.async.commit_group;" ::: "memory");
    asm volatile("cp.async.wait_group 0;" ::: "memory");
    __syncthreads();

    const int NCH = Sd / 64;   // 8
    for (int c = 0; c < NCH; c++) {
        int buf = c & 1;
        if (c + 1 < NCH) {
            loadA(c + 1, buf ^ 1);
            loadB(c + 1, buf ^ 1);
            asm volatile("cp.async.commit_group;" ::: "memory");
        }
        u32 base = sb + buf * GG_STG;
#pragma unroll
        for (int ks = 0; ks < 4; ks++) {
            int g = ks * 2 + lh;
            u32 ah[2][4], al[2][4];
#pragma unroll
            for (int mt = 0; mt < 2; mt++) {
                int row = warp_m * 32 + mt * 16 + lt;
                ldm4(ah[mt], base + GG_AHI + toff(row, g));
                ldm4(al[mt], base + GG_ALO + toff(row, g));
            }
#pragma unroll
            for (int nb = 0; nb < 2; nb++) {
                int nrow = warp_n * 32 + nb * 16 + lt;
                u32 bh[4];
                ldm4(bh, base + GG_B + toff(nrow, g));
#pragma unroll
                for (int mt = 0; mt < 2; mt++)
#pragma unroll
                    for (int s = 0; s < 2; s++) {
                        float* cc = acc[mt][nb * 2 + s];
                        mma16816(cc, ah[mt], bh[s], bh[s + 2]);
                        mma16816(cc, al[mt], bh[s], bh[s + 2]);
                    }
            }
        }
        asm volatile("cp.async.wait_group 0;" ::: "memory");
        __syncthreads();
    }

    // epilogue: g_G = acc * (64*invn[b]) + 64*b1[o]
#pragma unroll
    for (int mt = 0; mt < 2; mt++) {
        int r0r = b0 + warp_m * 32 + mt * 16 + (lane >> 2);
        float i0 = g_invn[r0r] * 64.0f;
        float i1 = g_invn[r0r + 8] * 64.0f;
#pragma unroll
        for (int nt = 0; nt < 4; nt++) {
            int n = o0 + warp_n * 32 + nt * 8 + (lane & 3) * 2;
            float bb0 = 64.0f * __ldg(b1 + n);
            float bb1 = 64.0f * __ldg(b1 + n + 1);
            const float* cc = acc[mt][nt];
            float2 v0 = make_float2(fmaf(cc[0], i0, bb0), fmaf(cc[1], i0, bb1));
            float2 v1 = make_float2(fmaf(cc[2], i1, bb0), fmaf(cc[3], i1, bb1));
            *(float2*)&g_G[(size_t)r0r * H1d + n] = v0;
            *(float2*)&g_G[(size_t)(r0r + 8) * H1d + n] = v1;
        }
    }
}

// ---------------------------------------------------------------------------
// k_genA: one warp per (b, a) row. h64[o] = relu(g64[b][o] + 64*inv*awt[a][o])
// -> fp16 row of g_h1, plus g_rinv = 1/(||h64|| + 64*eps).
// ---------------------------------------------------------------------------
__global__ void __launch_bounds__(256) k_genA() {
    int w    = (blockIdx.x * blockDim.x + threadIdx.x) >> 5;
    int lane = threadIdx.x & 31;
    if (w >= NROWS) return;
    int b = w >> 6, a = w & 63;
    float inv64 = g_invn[b] * 64.0f;
    const float*  g  = g_G + (size_t)b * H1d;
    const __half* aw = g_AWTt2 + (size_t)a * H1d;
    __half* dst = g_h1 + (size_t)w * H1d;

    float ss = 0.f;
#pragma unroll
    for (int it = 0; it < 4; it++) {
        int o = it * 256 + lane * 8;
        float4 g0 = *(const float4*)(g + o);
        float4 g1 = *(const float4*)(g + o + 4);
        uint4 wq = *(const uint4*)(aw + o);
        float2 w01 = __half22float2(*(const __half2*)&wq.x);
        float2 w23 = __half22float2(*(const __half2*)&wq.y);
        float2 w45 = __half22float2(*(const __half2*)&wq.z);
        float2 w67 = __half22float2(*(const __half2*)&wq.w);
        float h[8];
        h[0] = fmaxf(fmaf(inv64, w01.x, g0.x), 0.f);
        h[1] = fmaxf(fmaf(inv64, w01.y, g0.y), 0.f);
        h[2] = fmaxf(fmaf(inv64, w23.x, g0.z), 0.f);
        h[3] = fmaxf(fmaf(inv64, w23.y, g0.w), 0.f);
        h[4] = fmaxf(fmaf(inv64, w45.x, g1.x), 0.f);
        h[5] = fmaxf(fmaf(inv64, w45.y, g1.y), 0.f);
        h[6] = fmaxf(fmaf(inv64, w67.x, g1.z), 0.f);
        h[7] = fmaxf(fmaf(inv64, w67.y, g1.w), 0.f);
#pragma unroll
        for (int j = 0; j < 8; j++) ss = fmaf(h[j], h[j], ss);
        uint4 q;
        q.x = pkhf(h[0], h[1]); q.y = pkhf(h[2], h[3]);
        q.z = pkhf(h[4], h[5]); q.w = pkhf(h[6], h[7]);
        *(uint4*)(dst + o) = q;
    }
#pragma unroll
    for (int off = 16; off; off >>= 1) ss += __shfl_xor_sync(0xffffffffu, ss, off);
    if (lane == 0) g_rinv[w] = 1.f / (sqrtf(ss) + 64.0f * EPSf);
}

// ---------------------------------------------------------------------------
// Main kernel (R15-proven): pure GEMM. M=64 rows/CTA, N=512 in 2 passes of
// 256, K=1024 in 16 chunks of 64. 256 threads, 2 CTAs/SM.
// ---------------------------------------------------------------------------
#define SOFF_B2    0        // 512 f32
#define SOFF_WQ    2048     // 512 f32
#define SOFF_RINV  4096     // 64 f32
#define SOFF_SS    4352     // 256 f32 (q cross-warp partials)
#define SOFF_STG   6144
#define AF_OFF     0        // 64 rows x 128B = 8 KB
#define BF_OFF     8192     // 256 rows x 128B = 32 KB
#define STG_BYTES  40960    // 40 KB per stage
#define SMEM_TOTAL (SOFF_STG + 2 * STG_BYTES)   // 88064 B -> 2 CTAs = 172 KB

#define KC  64
#define NCH (H1d / KC)      // 16 chunks per pass

__global__ void __launch_bounds__(256, 2)
k_main(const float* __restrict__ b2, const float* __restrict__ Wq,
       const float* __restrict__ bq, float* __restrict__ out) {
    extern __shared__ __align__(1024) char smem[];
    u32 sb = smem_u32(smem);
    int tid = threadIdx.x;
    int wid = tid >> 5, lane = tid & 31;
    int warp_m = wid >> 2, warp_n = wid & 3;       // 2 x 4 warp grid
    int bidx = blockIdx.x;
    int r0 = bidx * 64;

    float* b2s   = (float*)(smem + SOFF_B2);
    float* wqs   = (float*)(smem + SOFF_WQ);
    float* rinvs = (float*)(smem + SOFF_RINV);
    float* sss   = (float*)(smem + SOFF_SS);

    for (int i = tid; i < H2d; i += 256) { b2s[i] = b2[i]; wqs[i] = Wq[i]; }
    if (tid < 64) rinvs[tid] = g_rinv[r0 + tid];
    __syncthreads();

    // A loader: 64 rows x 64 k fp16 per chunk (8 KB)
    auto loadA = [&](int c, int buf) {
        u32 af = sb + SOFF_STG + buf * STG_BYTES + AF_OFF;
        const __half* h1 = g_h1 + (size_t)r0 * H1d + c * KC;
#pragma unroll
        for (int i = 0; i < 2; i++) {
            int e = tid + i * 256;
            int row = e >> 3, g = e & 7;
            cpasync16(af + toff(row, g), h1 + (size_t)row * H1d + g * 8);
        }
    };
    // B loader: W2 fp16, 256 n-rows x 64 k per chunk (32 KB)
    auto loadB = [&](int pass, int c, int buf) {
        u32 bf = sb + SOFF_STG + buf * STG_BYTES + BF_OFF;
        const __half* w2 = g_W2h + (size_t)(pass * 256) * H1d + c * KC;
#pragma unroll
        for (int i = 0; i < 8; i++) {
            int e = tid + i * 256;
            int n = e >> 3, g = e & 7;
            cpasync16(bf + toff(n, g), w2 + (size_t)n * H1d + g * 8);
        }
    };

    int lt = lane & 15, lh = lane >> 4;
    float qacc[4] = {0.f, 0.f, 0.f, 0.f};

    for (int pass = 0; pass < 2; pass++) {
        float acc[2][8][4];
#pragma unroll
        for (int i = 0; i < 2; i++)
#pragma unroll
            for (int j = 0; j < 8; j++)
#pragma unroll
                for (int k = 0; k < 4; k++) acc[i][j][k] = 0.f;

        loadA(0, 0);
        loadB(pass, 0, 0);
        asm volatile("cp.async.commit_group;" ::: "memory");
        asm volatile("cp.async.wait_group 0;" ::: "memory");
        __syncthreads();

        for (int c = 0; c < NCH; c++) {
            int buf = c & 1;
            bool more = (c + 1 < NCH);
            if (more) {
                loadA(c + 1, buf ^ 1);
                loadB(pass, c + 1, buf ^ 1);
                asm volatile("cp.async.commit_group;" ::: "memory");
            }

            u32 abase = sb + SOFF_STG + buf * STG_BYTES;
#pragma unroll
            for (int ks = 0; ks < 4; ks++) {
                int g = ks * 2 + lh;
                u32 ah[2][4];
#pragma unroll
                for (int mt = 0; mt < 2; mt++) {
                    int row = warp_m * 32 + mt * 16 + lt;
                    ldm4(ah[mt], abase + AF_OFF + toff(row, g));
                }
#pragma unroll
                for (int nb = 0; nb < 4; nb++) {
                    int nrow = warp_n * 64 + nb * 16 + lt;
                    u32 bh[4];
                    ldm4(bh, abase + BF_OFF + toff(nrow, g));
#pragma unroll
                    for (int mt = 0; mt < 2; mt++)
#pragma unroll
                        for (int s = 0; s < 2; s++)
                            mma16816(acc[mt][nb * 2 + s], ah[mt],
                                     bh[s], bh[s + 2]);
                }
            }
            asm volatile("cp.async.wait_group 0;" ::: "memory");
            __syncthreads();
        }

        // epilogue: q += relu(acc * rinv + b2) * Wq for this pass's 256 n
#pragma unroll
        for (int mt = 0; mt < 2; mt++) {
            int rlo = warp_m * 32 + mt * 16 + (lane >> 2);
            float rv0 = rinvs[rlo], rv1 = rinvs[rlo + 8];
#pragma unroll
            for (int nt = 0; nt < 8; nt++) {
                int n = pass * 256 + warp_n * 64 + nt * 8 + (lane & 3) * 2;
                float bb0 = b2s[n], bb1 = b2s[n + 1];
                float w0 = wqs[n], w1 = wqs[n + 1];
                const float* cc = acc[mt][nt];
                qacc[mt * 2 + 0] += fmaxf(fmaf(cc[0], rv0, bb0), 0.f) * w0 +
                                    fmaxf(fmaf(cc[1], rv0, bb1), 0.f) * w1;
                qacc[mt * 2 + 1] += fmaxf(fmaf(cc[2], rv1, bb0), 0.f) * w0 +
                                    fmaxf(fmaf(cc[3], rv1, bb1), 0.f) * w1;
            }
        }
    }

    // reduce q over the 4 lanes of each quad
#pragma unroll
    for (int off = 1; off <= 2; off <<= 1)
#pragma unroll
        for (int i = 0; i < 4; i++)
            qacc[i] += __shfl_xor_sync(0xffffffffu, qacc[i], off);

    __syncthreads();
    if ((lane & 3) == 0) {
#pragma unroll
        for (int mt = 0; mt < 2; mt++)
#pragma unroll
            for (int hh = 0; hh < 2; hh++) {
                int row = warp_m * 32 + mt * 16 + hh * 8 + (lane >> 2);
                sss[row * 4 + warp_n] = qacc[mt * 2 + hh];
            }
    }
    __syncthreads();
    if (tid < 64)
        out[r0 + tid] = sss[tid * 4] + sss[tid * 4 + 1] +
                        sss[tid * 4 + 2] + sss[tid * 4 + 3] + __ldg(bq);
}

// ---------------------------------------------------------------------------
extern "C" void kernel_launch(void* const* d_in, const int* in_sizes, int n_in,
                              void* d_out, int out_size) {
    const float* states = (const float*)d_in[0];
    const float* W1     = (const float*)d_in[1];
    const float* b1     = (const float*)d_in[2];
    const float* W2     = (const float*)d_in[3];
    const float* b2     = (const float*)d_in[4];
    const float* Wq     = (const float*)d_in[5];
    const float* bq     = (const float*)d_in[6];
    float* out = (float*)d_out;

    cudaFuncSetAttribute((const void*)k_main,
                         cudaFuncAttributeMaxDynamicSharedMemorySize, SMEM_TOTAL);
    cudaFuncSetAttribute((const void*)k_gemmG_tc,
                         cudaFuncAttributeMaxDynamicSharedMemorySize, GG_SMEM);

    k_invn<<<Bd / 8, 256>>>(states);
    k_prep<<<(Bd * Sd + 255) / 256, 256>>>(W1, W2, states);
    k_gemmG_tc<<<(Bd / 64) * (H1d / 128), 256, GG_SMEM>>>(b1);
    k_genA<<<NROWS / 8, 256>>>();
    k_main<<<Bd, 256, SMEM_TOTAL>>>(b2, Wq, bq, out);
}